// round 1
// baseline (speedup 1.0000x reference)
#include <cuda_runtime.h>

// Problem constants
#define NB 8       // batch
#define NC 256     // channels
#define NN 4096    // H*W
#define ND 8       // d_qk
#define BM 64      // query tile rows
#define BN 64      // key tile
#define SPITCH 72  // padded pitch for S/P tile (72%32==8 -> conflict-free patterns)

// Scratch (device globals; allocation APIs are forbidden)
__device__ float g_q[NB * NN * ND];                 // [b][n][d]
__device__ float g_k[NB * NN * ND];                 // [b][n][d]
__device__ float g_vt[(size_t)NB * NN * NC];        // [b][n][c]  (V transposed)

typedef unsigned long long u64;

__device__ __forceinline__ u64 pk(float a, float b) {
    u64 r; asm("mov.b64 %0, {%1,%2};" : "=l"(r) : "f"(a), "f"(b)); return r;
}
__device__ __forceinline__ void fma2(u64 &d, u64 a, u64 b) {
    asm("fma.rn.f32x2 %0, %1, %2, %0;" : "+l"(d) : "l"(a), "l"(b));
}
__device__ __forceinline__ void mul2(u64 &d, u64 a) {
    asm("mul.rn.f32x2 %0, %0, %1;" : "+l"(d) : "l"(a));
}
__device__ __forceinline__ float2 unpk(u64 v) {
    float2 r; asm("mov.b64 {%0,%1}, %2;" : "=f"(r.x), "=f"(r.y) : "l"(v)); return r;
}

// ---------------------------------------------------------------------------
// Kernel 1: Q/K projections. One thread per spatial position n.
// q[b,n,d] = sum_c wq[d,c]*x[b,c,n] + bq[d]   (same for k)
// ---------------------------------------------------------------------------
__global__ __launch_bounds__(256) void qk_proj_kernel(
    const float* __restrict__ x,
    const float* __restrict__ wq, const float* __restrict__ bq,
    const float* __restrict__ wk, const float* __restrict__ bk)
{
    __shared__ float swq[ND * NC];
    __shared__ float swk[ND * NC];
    int t = threadIdx.x;
    for (int i = t; i < ND * NC; i += 256) { swq[i] = wq[i]; swk[i] = wk[i]; }
    __syncthreads();

    int b = blockIdx.y;
    int n = blockIdx.x * 256 + t;
    const float* xp = x + (size_t)b * NC * NN + n;

    float qa[ND], ka[ND];
#pragma unroll
    for (int d = 0; d < ND; d++) { qa[d] = bq[d]; ka[d] = bk[d]; }

#pragma unroll 4
    for (int c = 0; c < NC; c++) {
        float xv = xp[(size_t)c * NN];
#pragma unroll
        for (int d = 0; d < ND; d++) {
            qa[d] = fmaf(swq[d * NC + c], xv, qa[d]);
            ka[d] = fmaf(swk[d * NC + c], xv, ka[d]);
        }
    }
    size_t base = ((size_t)b * NN + n) * ND;
#pragma unroll
    for (int d = 0; d < ND; d++) { g_q[base + d] = qa[d]; g_k[base + d] = ka[d]; }
}

// ---------------------------------------------------------------------------
// Kernel 2: V projection into transposed layout g_vt[b][n][co].
// Tiled SGEMM with packed f32x2 FMAs. CTA tile: 64 n x 64 co, K-chunks of 16.
// ---------------------------------------------------------------------------
__global__ __launch_bounds__(256) void v_proj_kernel(
    const float* __restrict__ x,
    const float* __restrict__ wv, const float* __restrict__ bv)
{
    __shared__ float Xs[16][64];  // [c][n]
    __shared__ float Ws[16][64];  // [c][co]

    int t   = threadIdx.x;
    int nb_ = blockIdx.x * 64;
    int cb  = blockIdx.y * 64;
    int b   = blockIdx.z;

    int tn  = t & 15;        // n-subtile  (4 rows: tn*4 + i)
    int tco = t >> 4;        // co-subtile (4 cols: tco*4 + j)

    u64 acc[4][2];
#pragma unroll
    for (int i = 0; i < 4; i++) { acc[i][0] = 0ULL; acc[i][1] = 0ULL; }

    for (int c0 = 0; c0 < NC; c0 += 16) {
        // Load X tile: coalesced over n
#pragma unroll
        for (int e = 0; e < 4; e++) {
            int lin = t + 256 * e;
            int cl = lin >> 6, nl = lin & 63;
            Xs[cl][nl] = x[((size_t)b * NC + c0 + cl) * NN + nb_ + nl];
        }
        // Load W tile transposed: conflict-free smem stores
#pragma unroll
        for (int e = 0; e < 4; e++) {
            int col = t & 63;
            int cl  = (t >> 6) + 4 * e;
            Ws[cl][col] = wv[(size_t)(cb + col) * NC + c0 + cl];
        }
        __syncthreads();

#pragma unroll
        for (int c = 0; c < 16; c++) {
            float4 xv = *(const float4*)&Xs[c][tn * 4];
            float4 wv4 = *(const float4*)&Ws[c][tco * 4];
            u64 w01 = pk(wv4.x, wv4.y);
            u64 w23 = pk(wv4.z, wv4.w);
            float xs[4] = {xv.x, xv.y, xv.z, xv.w};
#pragma unroll
            for (int i = 0; i < 4; i++) {
                u64 xp2 = pk(xs[i], xs[i]);
                fma2(acc[i][0], xp2, w01);
                fma2(acc[i][1], xp2, w23);
            }
        }
        __syncthreads();
    }

    float bvv[4];
#pragma unroll
    for (int j = 0; j < 4; j++) bvv[j] = bv[cb + tco * 4 + j];

#pragma unroll
    for (int i = 0; i < 4; i++) {
        int n = nb_ + tn * 4 + i;
        float2 a0 = unpk(acc[i][0]);
        float2 a1 = unpk(acc[i][1]);
        float4 o;
        o.x = a0.x + bvv[0]; o.y = a0.y + bvv[1];
        o.z = a1.x + bvv[2]; o.w = a1.y + bvv[3];
        *(float4*)&g_vt[((size_t)b * NN + n) * NC + cb + tco * 4] = o;
    }
}

// ---------------------------------------------------------------------------
// Kernel 3: flash attention + epilogue (gamma*out + x), fused.
// CTA: one batch b, 64 query rows. Streams key tiles of 64.
// Thread (tm,tc): 8 query rows (tm*8+i) x 8 output channels (tc*8+j).
// ---------------------------------------------------------------------------
#define FLASH_SMEM_FLOATS (BN * NC + BN * SPITCH + BM * ND + BN * ND + 3 * 64)
#define FLASH_SMEM_BYTES (FLASH_SMEM_FLOATS * 4)

__global__ __launch_bounds__(256, 2) void flash_kernel(
    const float* __restrict__ x,
    const float* __restrict__ gamma,
    float* __restrict__ out)
{
    extern __shared__ float smem[];
    float* Vs    = smem;                       // [BN][NC]
    float* Sp    = Vs + BN * NC;               // [BN][SPITCH]  (S then P, [n][m])
    float* Qs    = Sp + BN * SPITCH;           // [BM][ND]
    float* Ks    = Qs + BM * ND;               // [BN][ND]
    float* rmax  = Ks + BN * ND;               // [64]
    float* rsum  = rmax + 64;                  // [64]
    float* rcorr = rsum + 64;                  // [64]

    int t  = threadIdx.x;
    int b  = blockIdx.y;
    int m0 = blockIdx.x * BM;

    int tm = t >> 5, tc = t & 31;      // phase C mapping
    int ma = t & 63, nb = (t >> 6) * 16;  // phase A mapping
    int r  = t >> 2, q4 = t & 3;       // phase B mapping

    for (int i = t; i < BM * ND; i += 256) Qs[i] = g_q[((size_t)b * NN + m0) * ND + i];
    if (t < 64) { rmax[t] = -INFINITY; rsum[t] = 0.0f; }

    u64 acc[8][4];
#pragma unroll
    for (int i = 0; i < 8; i++)
#pragma unroll
        for (int j = 0; j < 4; j++) acc[i][j] = 0ULL;

    for (int jt = 0; jt < NN / BN; jt++) {
        int kn0 = jt * BN;
        // Load K tile and V tile
        for (int i = t; i < BN * ND; i += 256) Ks[i] = g_k[((size_t)b * NN + kn0) * ND + i];
        {
            const float4* vsrc = (const float4*)(g_vt + ((size_t)b * NN + kn0) * NC);
            float4* vdst = (float4*)Vs;
#pragma unroll
            for (int e = 0; e < 16; e++) {
                int lin = t + 256 * e;
                vdst[lin] = vsrc[lin];
            }
        }
        __syncthreads();

        // ---- Phase A: S[m][n] = q[m].k[n], stored transposed Sp[n][m] ----
        {
            float4 q0 = *(const float4*)&Qs[ma * ND];
            float4 q1 = *(const float4*)&Qs[ma * ND + 4];
#pragma unroll
            for (int nn = 0; nn < 16; nn++) {
                int n = nb + nn;
                float4 k0 = *(const float4*)&Ks[n * ND];
                float4 k1 = *(const float4*)&Ks[n * ND + 4];
                float s = q0.x * k0.x + q0.y * k0.y + q0.z * k0.z + q0.w * k0.w
                        + q1.x * k1.x + q1.y * k1.y + q1.z * k1.z + q1.w * k1.w;
                Sp[n * SPITCH + ma] = s;
            }
        }
        __syncthreads();

        // ---- Phase B: online softmax (4 threads per row, n = i*4+q4) ----
        {
            float sv[16];
            float lmax = -INFINITY;
#pragma unroll
            for (int i = 0; i < 16; i++) {
                sv[i] = Sp[(i * 4 + q4) * SPITCH + r];
                lmax = fmaxf(lmax, sv[i]);
            }
            lmax = fmaxf(lmax, __shfl_xor_sync(0xffffffffu, lmax, 1, 4));
            lmax = fmaxf(lmax, __shfl_xor_sync(0xffffffffu, lmax, 2, 4));
            float mold = rmax[r];
            float mnew = fmaxf(mold, lmax);
            float lsum = 0.0f;
#pragma unroll
            for (int i = 0; i < 16; i++) {
                float p = __expf(sv[i] - mnew);
                Sp[(i * 4 + q4) * SPITCH + r] = p;
                lsum += p;
            }
            lsum += __shfl_xor_sync(0xffffffffu, lsum, 1, 4);
            lsum += __shfl_xor_sync(0xffffffffu, lsum, 2, 4);
            float cf = __expf(mold - mnew);
            if (q4 == 0) {
                rmax[r] = mnew;
                rsum[r] = rsum[r] * cf + lsum;
                rcorr[r] = cf;
            }
        }
        __syncthreads();

        // ---- Phase C: acc = acc*corr + P·V  (packed f32x2) ----
#pragma unroll
        for (int i = 0; i < 8; i++) {
            float cf = rcorr[tm * 8 + i];
            u64 cp = pk(cf, cf);
#pragma unroll
            for (int j = 0; j < 4; j++) mul2(acc[i][j], cp);
        }
        const float4* Vs4 = (const float4*)Vs;
        for (int n = 0; n < BN; n++) {
            float4 p0 = *(const float4*)&Sp[n * SPITCH + tm * 8];
            float4 p1 = *(const float4*)&Sp[n * SPITCH + tm * 8 + 4];
            float4 va = Vs4[n * (NC / 4) + tc * 2];
            float4 vb = Vs4[n * (NC / 4) + tc * 2 + 1];
            u64 v01 = pk(va.x, va.y), v23 = pk(va.z, va.w);
            u64 v45 = pk(vb.x, vb.y), v67 = pk(vb.z, vb.w);
            float pv[8] = {p0.x, p0.y, p0.z, p0.w, p1.x, p1.y, p1.z, p1.w};
#pragma unroll
            for (int i = 0; i < 8; i++) {
                u64 pp = pk(pv[i], pv[i]);
                fma2(acc[i][0], pp, v01);
                fma2(acc[i][1], pp, v23);
                fma2(acc[i][2], pp, v45);
                fma2(acc[i][3], pp, v67);
            }
        }
        __syncthreads();
    }

    // ---- Epilogue: out[b,c,m] = gamma * (acc/row_sum) + x[b,c,m] ----
    float gm = *gamma;
    float inv[8];
#pragma unroll
    for (int i = 0; i < 8; i++) inv[i] = 1.0f / rsum[tm * 8 + i];

    float2 a[8][4];
#pragma unroll
    for (int i = 0; i < 8; i++)
#pragma unroll
        for (int j = 0; j < 4; j++) a[i][j] = unpk(acc[i][j]);

#pragma unroll
    for (int jj = 0; jj < 4; jj++) {
#pragma unroll
        for (int h = 0; h < 2; h++) {
            int c = tc * 8 + jj * 2 + h;
            size_t base = ((size_t)b * NC + c) * NN + m0 + tm * 8;
            float4 x0 = *(const float4*)(x + base);
            float4 x1 = *(const float4*)(x + base + 4);
            float4 o0, o1;
            o0.x = gm * (h ? a[0][jj].y : a[0][jj].x) * inv[0] + x0.x;
            o0.y = gm * (h ? a[1][jj].y : a[1][jj].x) * inv[1] + x0.y;
            o0.z = gm * (h ? a[2][jj].y : a[2][jj].x) * inv[2] + x0.z;
            o0.w = gm * (h ? a[3][jj].y : a[3][jj].x) * inv[3] + x0.w;
            o1.x = gm * (h ? a[4][jj].y : a[4][jj].x) * inv[4] + x1.x;
            o1.y = gm * (h ? a[5][jj].y : a[5][jj].x) * inv[5] + x1.y;
            o1.z = gm * (h ? a[6][jj].y : a[6][jj].x) * inv[6] + x1.z;
            o1.w = gm * (h ? a[7][jj].y : a[7][jj].x) * inv[7] + x1.w;
            *(float4*)(out + base) = o0;
            *(float4*)(out + base + 4) = o1;
        }
    }
}

// ---------------------------------------------------------------------------
extern "C" void kernel_launch(void* const* d_in, const int* in_sizes, int n_in,
                              void* d_out, int out_size)
{
    const float* x     = (const float*)d_in[0];
    const float* wq    = (const float*)d_in[1];
    const float* bq    = (const float*)d_in[2];
    const float* wk    = (const float*)d_in[3];
    const float* bk    = (const float*)d_in[4];
    const float* wv    = (const float*)d_in[5];
    const float* bv    = (const float*)d_in[6];
    const float* gamma = (const float*)d_in[7];
    float* out = (float*)d_out;

    cudaFuncSetAttribute(flash_kernel,
                         cudaFuncAttributeMaxDynamicSharedMemorySize,
                         FLASH_SMEM_BYTES);

    qk_proj_kernel<<<dim3(NN / 256, NB), 256>>>(x, wq, bq, wk, bk);
    v_proj_kernel<<<dim3(NN / 64, NC / 64, NB), 256>>>(x, wv, bv);
    flash_kernel<<<dim3(NN / BM, NB), 256, FLASH_SMEM_BYTES>>>(x, gamma, out);
}

// round 3
// speedup vs baseline: 2.4296x; 2.4296x over previous
#include <cuda_runtime.h>
#include <cuda_bf16.h>
#include <cstdint>

// Problem constants
#define NB 8       // batch
#define NC 256     // channels
#define NN 4096    // H*W
#define ND 8       // d_qk
#define BM 128     // query rows per CTA
#define BN2 64     // key tile
#define NTILES (NN / BN2)

typedef unsigned long long u64;
typedef unsigned int u32;

// Scratch (device globals; allocation APIs are forbidden)
__device__ float g_q[NB * NN * ND];                      // [b][n][d]
__device__ float g_k[NB * NN * ND];                      // [b][n][d]
__device__ __nv_bfloat16 g_vhi[(size_t)NB * NC * NN];    // [b][c][n]
__device__ __nv_bfloat16 g_vlo[(size_t)NB * NC * NN];    // [b][c][n]

// ---------------- helpers ----------------
__device__ __forceinline__ u64 pk(float a, float b) {
    u64 r; asm("mov.b64 %0, {%1,%2};" : "=l"(r) : "f"(a), "f"(b)); return r;
}
__device__ __forceinline__ void fma2(u64 &d, u64 a, u64 b) {
    asm("fma.rn.f32x2 %0, %1, %2, %0;" : "+l"(d) : "l"(a), "l"(b));
}
__device__ __forceinline__ float2 unpk(u64 v) {
    float2 r; asm("mov.b64 {%0,%1}, %2;" : "=f"(r.x), "=f"(r.y) : "l"(v)); return r;
}
// pack: lower 16 bits = first arg (lower address on store)
__device__ __forceinline__ u32 bf2(float lo, float hi) {
    u32 r; asm("cvt.rn.bf16x2.f32 %0, %1, %2;" : "=r"(r) : "f"(hi), "f"(lo)); return r;
}
__device__ __forceinline__ float bflo(u32 w) { return __uint_as_float(w << 16); }
__device__ __forceinline__ float bfhi(u32 w) { return __uint_as_float(w & 0xffff0000u); }

__device__ __forceinline__ u32 smem_u32(const void* p) {
    u32 a; asm("{ .reg .u64 t; cvta.to.shared.u64 t, %1; cvt.u32.u64 %0, t; }" : "=r"(a) : "l"(p));
    return a;
}
__device__ __forceinline__ void ldmx4(u32 a, u32 &r0, u32 &r1, u32 &r2, u32 &r3) {
    asm volatile("ldmatrix.sync.aligned.m8n8.x4.shared.b16 {%0,%1,%2,%3}, [%4];"
                 : "=r"(r0), "=r"(r1), "=r"(r2), "=r"(r3) : "r"(a));
}
__device__ __forceinline__ void ldmx2(u32 a, u32 &r0, u32 &r1) {
    asm volatile("ldmatrix.sync.aligned.m8n8.x2.shared.b16 {%0,%1}, [%2];"
                 : "=r"(r0), "=r"(r1) : "r"(a));
}
__device__ __forceinline__ void mma16816(float* d, u32 a0, u32 a1, u32 a2, u32 a3,
                                         u32 b0, u32 b1) {
    asm volatile(
        "mma.sync.aligned.m16n8k16.row.col.f32.bf16.bf16.f32 "
        "{%0,%1,%2,%3}, {%4,%5,%6,%7}, {%8,%9}, {%0,%1,%2,%3};"
        : "+f"(d[0]), "+f"(d[1]), "+f"(d[2]), "+f"(d[3])
        : "r"(a0), "r"(a1), "r"(a2), "r"(a3), "r"(b0), "r"(b1));
}

// ---------------------------------------------------------------------------
// Kernel 1: Q/K projections (unchanged, passing).
// ---------------------------------------------------------------------------
__global__ __launch_bounds__(256) void qk_proj_kernel(
    const float* __restrict__ x,
    const float* __restrict__ wq, const float* __restrict__ bq,
    const float* __restrict__ wk, const float* __restrict__ bk)
{
    __shared__ float swq[ND * NC];
    __shared__ float swk[ND * NC];
    int t = threadIdx.x;
    for (int i = t; i < ND * NC; i += 256) { swq[i] = wq[i]; swk[i] = wk[i]; }
    __syncthreads();

    int b = blockIdx.y;
    int n = blockIdx.x * 256 + t;
    const float* xp = x + (size_t)b * NC * NN + n;

    float qa[ND], ka[ND];
#pragma unroll
    for (int d = 0; d < ND; d++) { qa[d] = bq[d]; ka[d] = bk[d]; }

#pragma unroll 4
    for (int c = 0; c < NC; c++) {
        float xv = xp[(size_t)c * NN];
#pragma unroll
        for (int d = 0; d < ND; d++) {
            qa[d] = fmaf(swq[d * NC + c], xv, qa[d]);
            ka[d] = fmaf(swk[d * NC + c], xv, ka[d]);
        }
    }
    size_t base = ((size_t)b * NN + n) * ND;
#pragma unroll
    for (int d = 0; d < ND; d++) { g_q[base + d] = qa[d]; g_k[base + d] = ka[d]; }
}

// ---------------------------------------------------------------------------
// Kernel 2: V projection -> bf16 hi/lo planes in natural [b][c][n] layout.
// ---------------------------------------------------------------------------
__global__ __launch_bounds__(256) void v_proj_kernel(
    const float* __restrict__ x,
    const float* __restrict__ wv, const float* __restrict__ bv)
{
    __shared__ float Xs[16][64];  // [c][n]
    __shared__ float Ws[16][64];  // [c][co]

    int t   = threadIdx.x;
    int nb_ = blockIdx.x * 64;
    int cb  = blockIdx.y * 64;
    int b   = blockIdx.z;

    int tn  = t & 15;
    int tco = t >> 4;

    u64 acc[4][2];
#pragma unroll
    for (int i = 0; i < 4; i++) { acc[i][0] = 0ULL; acc[i][1] = 0ULL; }

    for (int c0 = 0; c0 < NC; c0 += 16) {
#pragma unroll
        for (int e = 0; e < 4; e++) {
            int lin = t + 256 * e;
            int cl = lin >> 6, nl = lin & 63;
            Xs[cl][nl] = x[((size_t)b * NC + c0 + cl) * NN + nb_ + nl];
        }
#pragma unroll
        for (int e = 0; e < 4; e++) {
            int col = t & 63;
            int cl  = (t >> 6) + 4 * e;
            Ws[cl][col] = wv[(size_t)(cb + col) * NC + c0 + cl];
        }
        __syncthreads();

#pragma unroll
        for (int c = 0; c < 16; c++) {
            float4 xv = *(const float4*)&Xs[c][tn * 4];
            float4 wv4 = *(const float4*)&Ws[c][tco * 4];
            u64 w01 = pk(wv4.x, wv4.y);
            u64 w23 = pk(wv4.z, wv4.w);
            float xs[4] = {xv.x, xv.y, xv.z, xv.w};
#pragma unroll
            for (int i = 0; i < 4; i++) {
                u64 xp2 = pk(xs[i], xs[i]);
                fma2(acc[i][0], xp2, w01);
                fma2(acc[i][1], xp2, w23);
            }
        }
        __syncthreads();
    }

    float bvv[4];
#pragma unroll
    for (int j = 0; j < 4; j++) bvv[j] = bv[cb + tco * 4 + j];

    float vals[4][4];  // [i = n offset][jc = c offset]
#pragma unroll
    for (int i = 0; i < 4; i++) {
        float2 a0 = unpk(acc[i][0]);
        float2 a1 = unpk(acc[i][1]);
        vals[i][0] = a0.x + bvv[0];
        vals[i][1] = a0.y + bvv[1];
        vals[i][2] = a1.x + bvv[2];
        vals[i][3] = a1.y + bvv[3];
    }
#pragma unroll
    for (int jc = 0; jc < 4; jc++) {
        u32 wh0 = bf2(vals[0][jc], vals[1][jc]);
        u32 wh1 = bf2(vals[2][jc], vals[3][jc]);
        u32 wl0 = bf2(vals[0][jc] - bflo(wh0), vals[1][jc] - bfhi(wh0));
        u32 wl1 = bf2(vals[2][jc] - bflo(wh1), vals[3][jc] - bfhi(wh1));
        size_t e = ((size_t)b * NC + cb + tco * 4 + jc) * NN + nb_ + tn * 4;
        *(uint2*)((void*)(g_vhi + e)) = make_uint2(wh0, wh1);
        *(uint2*)((void*)(g_vlo + e)) = make_uint2(wl0, wl1);
    }
}

// ---------------------------------------------------------------------------
// Kernel 3: flash attention with mma.sync (HMMA bf16) for P·V.
// CTA: batch b, 128 query rows. Warp w owns m-block (w>>2)*64, c-block (w&3)*64.
// D accumulates in registers over all 64 key tiles (no-max softmax, fp32 acc).
// V uses bf16 hi+lo split (2 MMAs) for fp32-grade precision.
// ---------------------------------------------------------------------------
#define OFF_RS   0                    // 256 f32 (row sums; used only at end)
#define OFF_K    1024                 // 64 x 8 f32 = 2 KB
#define OFF_P    3072                 // [128][64] bf16 swizzled = 16 KB
#define OFF_VHI  19456                // [256][64] bf16 swizzled = 32 KB
#define OFF_VLO  52224                // [256][64] bf16 swizzled = 32 KB
#define FLASH_SMEM 84992

__global__ __launch_bounds__(256, 1) void flash_mma_kernel(
    const float* __restrict__ x,
    const float* __restrict__ gamma,
    float* __restrict__ out)
{
    extern __shared__ char sm[];
    u32 sb = smem_u32(sm);
    int t = threadIdx.x, l = t & 31, w = t >> 5;
    int b = blockIdx.y, m0 = blockIdx.x * BM;
    int m = t & 127, half = t >> 7;
    int m_blk = (w >> 2) * 64, c_blk = (w & 3) * 64;

    const float4* qp = (const float4*)(g_q + ((size_t)b * NN + m0 + m) * ND);
    float4 q0 = qp[0], q1 = qp[1];
    float lsum = 0.0f;

    float acc[128];
#pragma unroll
    for (int i = 0; i < 128; i++) acc[i] = 0.0f;

    // per-lane ldmatrix address components
    u32 pbase = sb + OFF_P, vhib = sb + OFF_VHI, vlob = sb + OFF_VLO;
    int arow  = m_blk + (l & 15);
    u32 aswz  = (u32)((l & 7) << 4);
    u32 acolh = (u32)((l >> 4) << 4);     // 0 or 16 bytes (cols 0-7 / 8-15)
    int brow_l = l & 7;
    u32 bkh   = (u32)(((l >> 3) & 1) << 4);

    const __nv_bfloat16* vhg = g_vhi + (size_t)b * NC * NN;
    const __nv_bfloat16* vlg = g_vlo + (size_t)b * NC * NN;

    for (int j = 0; j < NTILES; j++) {
        __syncthreads();
        // K tile: 64 x 8 f32
        if (t < 128)
            ((float4*)(sm + OFF_K))[t] =
                ((const float4*)(g_k + ((size_t)b * NN + j * BN2) * ND))[t];
        // V tiles: 256 rows x 64 keys bf16 each, 128B rows, swizzled
#pragma unroll
        for (int e = 0; e < 8; e++) {
            int lin = e * 256 + t;
            int row = lin >> 3, c16 = lin & 7;
            u32 dof = (u32)(row * 128 + ((c16 * 16) ^ ((row & 7) << 4)));
            *(float4*)(sm + OFF_VHI + dof) =
                *(const float4*)(vhg + (size_t)row * NN + j * BN2 + c16 * 8);
            *(float4*)(sm + OFF_VLO + dof) =
                *(const float4*)(vlg + (size_t)row * NN + j * BN2 + c16 * 8);
        }
        __syncthreads();

        // S = q.k ; P = exp(S) rounded to bf16 ; lsum from rounded values
        {
            const float4* K4 = (const float4*)(sm + OFF_K);
#pragma unroll
            for (int g = 0; g < 4; g++) {
                float p[8];
#pragma unroll
                for (int uu = 0; uu < 8; uu++) {
                    int n = half * 32 + g * 8 + uu;
                    float4 k0 = K4[2 * n], k1 = K4[2 * n + 1];
                    float s = q0.x * k0.x + q0.y * k0.y + q0.z * k0.z + q0.w * k0.w
                            + q1.x * k1.x + q1.y * k1.y + q1.z * k1.z + q1.w * k1.w;
                    p[uu] = __expf(s);
                }
                uint4 pw;
                pw.x = bf2(p[0], p[1]); pw.y = bf2(p[2], p[3]);
                pw.z = bf2(p[4], p[5]); pw.w = bf2(p[6], p[7]);
                lsum += bflo(pw.x) + bfhi(pw.x) + bflo(pw.y) + bfhi(pw.y)
                      + bflo(pw.z) + bfhi(pw.z) + bflo(pw.w) + bfhi(pw.w);
                u32 cb = (u32)((half * 32 + g * 8) * 2);
                *(uint4*)(sm + OFF_P + m * 128 + (cb ^ ((m & 7) << 4))) = pw;
            }
        }
        __syncthreads();

        // MMA: acc[mt][ct] += P[m-tile][k] * Vhi/Vlo[c-tile][k]
#pragma unroll
        for (int ks = 0; ks < 4; ks++) {
            u32 af[4][4];
#pragma unroll
            for (int mt = 0; mt < 4; mt++) {
                u32 ad = pbase + (u32)((arow + mt * 16) * 128)
                       + (((u32)(ks * 32) + acolh) ^ aswz);
                ldmx4(ad, af[mt][0], af[mt][1], af[mt][2], af[mt][3]);
            }
#pragma unroll
            for (int ct = 0; ct < 8; ct++) {
                u32 brel = (u32)((c_blk + ct * 8 + brow_l) * 128)
                         + (((u32)(ks * 32) + bkh) ^ ((u32)brow_l << 4));
                u32 bh0, bh1, bl0, bl1;
                ldmx2(vhib + brel, bh0, bh1);
                ldmx2(vlob + brel, bl0, bl1);
#pragma unroll
                for (int mt = 0; mt < 4; mt++) {
                    float* d = &acc[(mt * 8 + ct) * 4];
                    mma16816(d, af[mt][0], af[mt][1], af[mt][2], af[mt][3], bh0, bh1);
                    mma16816(d, af[mt][0], af[mt][1], af[mt][2], af[mt][3], bl0, bl1);
                }
            }
        }
    }

    // Row sums -> inverse
    float* rs = (float*)sm;
    __syncthreads();
    rs[half * 128 + m] = lsum;
    __syncthreads();
    if (t < 128) rs[t] = 1.0f / (rs[t] + rs[t + 128]);
    __syncthreads();

    float gm = *gamma;

    // Epilogue: out[b,c,m] = gamma * acc * inv[m] + x[b,c,m]
#pragma unroll
    for (int mt = 0; mt < 4; mt++) {
        int r0 = m_blk + mt * 16 + (l >> 2);
        float s0 = gm * rs[r0];
        float s1 = gm * rs[r0 + 8];
#pragma unroll
        for (int ct = 0; ct < 8; ct++) {
            int c0 = c_blk + ct * 8 + (l & 3) * 2;
            const float* d = &acc[(mt * 8 + ct) * 4];
            size_t a0 = ((size_t)(b * NC + c0)) * NN + m0 + r0;
            size_t a1 = a0 + NN;
            out[a0]     = d[0] * s0 + x[a0];
            out[a1]     = d[1] * s0 + x[a1];
            out[a0 + 8] = d[2] * s1 + x[a0 + 8];
            out[a1 + 8] = d[3] * s1 + x[a1 + 8];
        }
    }
}

// ---------------------------------------------------------------------------
extern "C" void kernel_launch(void* const* d_in, const int* in_sizes, int n_in,
                              void* d_out, int out_size)
{
    const float* x     = (const float*)d_in[0];
    const float* wq    = (const float*)d_in[1];
    const float* bq    = (const float*)d_in[2];
    const float* wk    = (const float*)d_in[3];
    const float* bk    = (const float*)d_in[4];
    const float* wv    = (const float*)d_in[5];
    const float* bv    = (const float*)d_in[6];
    const float* gamma = (const float*)d_in[7];
    float* out = (float*)d_out;

    cudaFuncSetAttribute(flash_mma_kernel,
                         cudaFuncAttributeMaxDynamicSharedMemorySize,
                         FLASH_SMEM);

    qk_proj_kernel<<<dim3(NN / 256, NB), 256>>>(x, wq, bq, wk, bk);
    v_proj_kernel<<<dim3(NN / 64, NC / 64, NB), 256>>>(x, wv, bv);
    flash_mma_kernel<<<dim3(NN / BM, NB), 256, FLASH_SMEM>>>(x, gamma, out);
}

// round 6
// speedup vs baseline: 3.2236x; 1.3268x over previous
#include <cuda_runtime.h>
#include <cuda_bf16.h>
#include <cuda_fp16.h>
#include <cstdint>

// Problem constants
#define NB 8       // batch
#define NC 256     // channels
#define NN 4096    // H*W
#define ND 8       // d_qk
#define BM 128     // query rows per CTA
#define BN2 64     // key tile
#define NTILES (NN / BN2)
#define LOG2E 1.4426950408889634f

typedef unsigned long long u64;
typedef unsigned int u32;

// Scratch (device globals; allocation APIs are forbidden)
__device__ float g_q[NB * NN * ND];              // [b][n][d]
__device__ float g_k[NB * NN * ND];              // [b][n][d]
__device__ __half g_v[(size_t)NB * NC * NN];     // [b][c][n]  fp16 single plane

// ---------------- helpers ----------------
__device__ __forceinline__ u64 pk(float a, float b) {
    u64 r; asm("mov.b64 %0, {%1,%2};" : "=l"(r) : "f"(a), "f"(b)); return r;
}
__device__ __forceinline__ void fma2(u64 &d, u64 a, u64 b) {
    asm("fma.rn.f32x2 %0, %1, %2, %0;" : "+l"(d) : "l"(a), "l"(b));
}
__device__ __forceinline__ float2 unpk(u64 v) {
    float2 r; asm("mov.b64 {%0,%1}, %2;" : "=f"(r.x), "=f"(r.y) : "l"(v)); return r;
}
// pack fp16x2: lower 16 bits = first arg
__device__ __forceinline__ u32 f16x2(float lo, float hi) {
    u32 r; asm("cvt.rn.f16x2.f32 %0, %1, %2;" : "=r"(r) : "f"(hi), "f"(lo)); return r;
}
__device__ __forceinline__ float ex2f(float x) {
    float r; asm("ex2.approx.f32 %0, %1;" : "=f"(r) : "f"(x)); return r;
}
__device__ __forceinline__ u32 smem_u32(const void* p) {
    u32 a; asm("{ .reg .u64 t; cvta.to.shared.u64 t, %1; cvt.u32.u64 %0, t; }" : "=r"(a) : "l"(p));
    return a;
}
__device__ __forceinline__ void cpa16(u32 dst, const void* src) {
    asm volatile("cp.async.cg.shared.global [%0], [%1], 16;" :: "r"(dst), "l"(src));
}
__device__ __forceinline__ void ldmx4(u32 a, u32 &r0, u32 &r1, u32 &r2, u32 &r3) {
    asm volatile("ldmatrix.sync.aligned.m8n8.x4.shared.b16 {%0,%1,%2,%3}, [%4];"
                 : "=r"(r0), "=r"(r1), "=r"(r2), "=r"(r3) : "r"(a));
}
__device__ __forceinline__ void ldmx2(u32 a, u32 &r0, u32 &r1) {
    asm volatile("ldmatrix.sync.aligned.m8n8.x2.shared.b16 {%0,%1}, [%2];"
                 : "=r"(r0), "=r"(r1) : "r"(a));
}
__device__ __forceinline__ void mma16816(float* d, u32 a0, u32 a1, u32 a2, u32 a3,
                                         u32 b0, u32 b1) {
    asm volatile(
        "mma.sync.aligned.m16n8k16.row.col.f32.f16.f16.f32 "
        "{%0,%1,%2,%3}, {%4,%5,%6,%7}, {%8,%9}, {%0,%1,%2,%3};"
        : "+f"(d[0]), "+f"(d[1]), "+f"(d[2]), "+f"(d[3])
        : "r"(a0), "r"(a1), "r"(a2), "r"(a3), "r"(b0), "r"(b1));
}

// ---------------------------------------------------------------------------
// Kernel 1: Q/K projections.
// ---------------------------------------------------------------------------
__global__ __launch_bounds__(256) void qk_proj_kernel(
    const float* __restrict__ x,
    const float* __restrict__ wq, const float* __restrict__ bq,
    const float* __restrict__ wk, const float* __restrict__ bk)
{
    __shared__ float swq[ND * NC];
    __shared__ float swk[ND * NC];
    int t = threadIdx.x;
    for (int i = t; i < ND * NC; i += 256) { swq[i] = wq[i]; swk[i] = wk[i]; }
    __syncthreads();

    int b = blockIdx.y;
    int n = blockIdx.x * 256 + t;
    const float* xp = x + (size_t)b * NC * NN + n;

    float qa[ND], ka[ND];
#pragma unroll
    for (int d = 0; d < ND; d++) { qa[d] = bq[d]; ka[d] = bk[d]; }

#pragma unroll 4
    for (int c = 0; c < NC; c++) {
        float xv = xp[(size_t)c * NN];
#pragma unroll
        for (int d = 0; d < ND; d++) {
            qa[d] = fmaf(swq[d * NC + c], xv, qa[d]);
            ka[d] = fmaf(swk[d * NC + c], xv, ka[d]);
        }
    }
    size_t base = ((size_t)b * NN + n) * ND;
#pragma unroll
    for (int d = 0; d < ND; d++) { g_q[base + d] = qa[d]; g_k[base + d] = ka[d]; }
}

// ---------------------------------------------------------------------------
// Kernel 2: V projection -> fp16 in natural [b][c][n] layout.
// ---------------------------------------------------------------------------
__global__ __launch_bounds__(256) void v_proj_kernel(
    const float* __restrict__ x,
    const float* __restrict__ wv, const float* __restrict__ bv)
{
    __shared__ float Xs[16][64];  // [c][n]
    __shared__ float Ws[16][64];  // [c][co]

    int t   = threadIdx.x;
    int nb_ = blockIdx.x * 64;
    int cb  = blockIdx.y * 64;
    int b   = blockIdx.z;

    int tn  = t & 15;
    int tco = t >> 4;

    u64 acc[4][2];
#pragma unroll
    for (int i = 0; i < 4; i++) { acc[i][0] = 0ULL; acc[i][1] = 0ULL; }

    for (int c0 = 0; c0 < NC; c0 += 16) {
#pragma unroll
        for (int e = 0; e < 4; e++) {
            int lin = t + 256 * e;
            int cl = lin >> 6, nl = lin & 63;
            Xs[cl][nl] = x[((size_t)b * NC + c0 + cl) * NN + nb_ + nl];
        }
#pragma unroll
        for (int e = 0; e < 4; e++) {
            int col = t & 63;
            int cl  = (t >> 6) + 4 * e;
            Ws[cl][col] = wv[(size_t)(cb + col) * NC + c0 + cl];
        }
        __syncthreads();

#pragma unroll
        for (int c = 0; c < 16; c++) {
            float4 xv = *(const float4*)&Xs[c][tn * 4];
            float4 wv4 = *(const float4*)&Ws[c][tco * 4];
            u64 w01 = pk(wv4.x, wv4.y);
            u64 w23 = pk(wv4.z, wv4.w);
            float xs[4] = {xv.x, xv.y, xv.z, xv.w};
#pragma unroll
            for (int i = 0; i < 4; i++) {
                u64 xp2 = pk(xs[i], xs[i]);
                fma2(acc[i][0], xp2, w01);
                fma2(acc[i][1], xp2, w23);
            }
        }
        __syncthreads();
    }

    float bvv[4];
#pragma unroll
    for (int j = 0; j < 4; j++) bvv[j] = bv[cb + tco * 4 + j];

    float vals[4][4];  // [i = n offset][jc = c offset]
#pragma unroll
    for (int i = 0; i < 4; i++) {
        float2 a0 = unpk(acc[i][0]);
        float2 a1 = unpk(acc[i][1]);
        vals[i][0] = a0.x + bvv[0];
        vals[i][1] = a0.y + bvv[1];
        vals[i][2] = a1.x + bvv[2];
        vals[i][3] = a1.y + bvv[3];
    }
#pragma unroll
    for (int jc = 0; jc < 4; jc++) {
        u32 w0 = f16x2(vals[0][jc], vals[1][jc]);
        u32 w1 = f16x2(vals[2][jc], vals[3][jc]);
        size_t e = ((size_t)b * NC + cb + tco * 4 + jc) * NN + nb_ + tn * 4;
        *(uint2*)((void*)(g_v + e)) = make_uint2(w0, w1);
    }
}

// ---------------------------------------------------------------------------
// Kernel 3: flash attention, fp16 HMMA single-plane P·V.
// K (whole batch row-set) resident in smem. Pass A: exact row max (scalar).
// Pass B: per 64-key tile, scalar S/exp -> fp16 P; V via cp.async double
// buffer; 128 HMMA/warp/tile. Warp w: m_blk=(w>>2)*64, c_blk=(w&3)*64.
// ---------------------------------------------------------------------------
#define OFF_K   0                     // 4096 x 8 f32 = 131072
#define OFF_P   131072                // 2 x [128][64] fp16 = 2 x 16384
#define OFF_V   163840                // 2 x [256][64] fp16 = 2 x 32768
#define OFF_RS  229376                // 256 f32 = 1024 B
#define FLASH_SMEM 230400

__global__ __launch_bounds__(256, 1) void flash_mma_kernel(
    const float* __restrict__ x,
    const float* __restrict__ gamma,
    float* __restrict__ out)
{
    extern __shared__ char sm[];
    u32 sb = smem_u32(sm);
    int t = threadIdx.x, l = t & 31, w = t >> 5;
    int b = blockIdx.y, m0 = blockIdx.x * BM;
    int m = t & 127, half = t >> 7;
    int m_blk = (w >> 2) * 64, c_blk = (w & 3) * 64;

    // Load K for whole batch into smem (8192 float4)
    {
        const float4* ksrc = (const float4*)(g_k + (size_t)b * NN * ND);
        float4* kdst = (float4*)(sm + OFF_K);
        for (int i = t; i < NN * ND / 4; i += 256) kdst[i] = ksrc[i];
    }

    // Q (scaled by log2e so exp = single ex2)
    const float4* qp = (const float4*)(g_q + ((size_t)b * NN + m0 + m) * ND);
    float4 q0 = qp[0], q1 = qp[1];
    q0.x *= LOG2E; q0.y *= LOG2E; q0.z *= LOG2E; q0.w *= LOG2E;
    q1.x *= LOG2E; q1.y *= LOG2E; q1.z *= LOG2E; q1.w *= LOG2E;
    __syncthreads();

    const float4* K4 = (const float4*)(sm + OFF_K);
    float* rs = (float*)(sm + OFF_RS);

    // ---- Pass A: exact row max (in log2 units) over this thread's half ----
    float mx8[8];
#pragma unroll
    for (int i = 0; i < 8; i++) mx8[i] = -1e30f;
    for (int j = 0; j < NTILES; j++) {
        int nk0 = j * BN2 + half * 32;
#pragma unroll
        for (int v = 0; v < 32; v++) {
            float4 k0 = K4[2 * (nk0 + v)], k1 = K4[2 * (nk0 + v) + 1];
            float s = q0.x * k0.x + q0.y * k0.y + q0.z * k0.z + q0.w * k0.w
                    + q1.x * k1.x + q1.y * k1.y + q1.z * k1.z + q1.w * k1.w;
            mx8[v & 7] = fmaxf(mx8[v & 7], s);
        }
    }
    float mxL = fmaxf(fmaxf(fmaxf(mx8[0], mx8[1]), fmaxf(mx8[2], mx8[3])),
                      fmaxf(fmaxf(mx8[4], mx8[5]), fmaxf(mx8[6], mx8[7])));
    rs[half * 128 + m] = mxL;
    __syncthreads();
    mxL = fmaxf(rs[m], rs[128 + m]);
    __syncthreads();

    float lsum = 0.0f;
    float acc[128];
#pragma unroll
    for (int i = 0; i < 128; i++) acc[i] = 0.0f;

    const __half* vg = g_v + (size_t)b * NC * NN;

    // per-lane ldmatrix address components
    u32 pbase = sb + OFF_P, vbase = sb + OFF_V;
    int arow  = m_blk + (l & 15);
    u32 aswz  = (u32)((l & 7) << 4);
    u32 acolh = (u32)((l >> 4) << 4);
    int brow_l = l & 7;
    u32 bkh   = (u32)(((l >> 3) & 1) << 4);

    // ---- helpers as lambdas ----
    auto loadV = [&](int j, int buf) {
        u32 vd = vbase + (u32)buf * 32768;
        const __half* vsrc = vg + j * BN2;
#pragma unroll
        for (int e = 0; e < 8; e++) {
            int lin = e * 256 + t;
            int row = lin >> 3, c16 = lin & 7;
            u32 dof = (u32)(row * 128 + ((c16 * 16) ^ ((row & 7) << 4)));
            cpa16(vd + dof, vsrc + (size_t)row * NN + c16 * 8);
        }
        asm volatile("cp.async.commit_group;" ::: "memory");
    };
    auto scalarP = [&](int j, int buf) {
        char* pd = sm + OFF_P + buf * 16384;
        int nk0 = j * BN2 + half * 32;
#pragma unroll
        for (int g = 0; g < 4; g++) {
            float p[8];
#pragma unroll
            for (int uu = 0; uu < 8; uu++) {
                int nk = nk0 + g * 8 + uu;
                float4 k0 = K4[2 * nk], k1 = K4[2 * nk + 1];
                float s = q0.x * k0.x + q0.y * k0.y + q0.z * k0.z + q0.w * k0.w
                        + q1.x * k1.x + q1.y * k1.y + q1.z * k1.z + q1.w * k1.w;
                p[uu] = ex2f(s - mxL);
            }
            uint4 pw;
            pw.x = f16x2(p[0], p[1]); pw.y = f16x2(p[2], p[3]);
            pw.z = f16x2(p[4], p[5]); pw.w = f16x2(p[6], p[7]);
            // sum of ROUNDED values (normalization cancels P rounding)
            {
                __half2 h0 = *(__half2*)&pw.x, h1 = *(__half2*)&pw.y;
                __half2 h2 = *(__half2*)&pw.z, h3 = *(__half2*)&pw.w;
                float2 f0 = __half22float2(h0), f1 = __half22float2(h1);
                float2 f2 = __half22float2(h2), f3 = __half22float2(h3);
                lsum += (f0.x + f0.y) + (f1.x + f1.y)
                      + (f2.x + f2.y) + (f3.x + f3.y);
            }
            u32 cb = (u32)((half * 32 + g * 8) * 2);
            *(uint4*)(pd + m * 128 + (cb ^ ((m & 7) << 4))) = pw;
        }
    };

    // ---- pipeline prologue ----
    loadV(0, 0);
    scalarP(0, 0);
    asm volatile("cp.async.wait_group 0;" ::: "memory");
    __syncthreads();

    for (int j = 0; j < NTILES; j++) {
        int buf = j & 1;
        if (j + 1 < NTILES) loadV(j + 1, buf ^ 1);

        // MMA(j)
        u32 pb = pbase + (u32)buf * 16384;
        u32 vb = vbase + (u32)buf * 32768;
#pragma unroll
        for (int ks = 0; ks < 4; ks++) {
            u32 af[4][4];
#pragma unroll
            for (int mt = 0; mt < 4; mt++) {
                u32 ad = pb + (u32)((arow + mt * 16) * 128)
                       + (((u32)(ks * 32) + acolh) ^ aswz);
                ldmx4(ad, af[mt][0], af[mt][1], af[mt][2], af[mt][3]);
            }
#pragma unroll
            for (int ct = 0; ct < 8; ct++) {
                u32 brel = (u32)((c_blk + ct * 8 + brow_l) * 128)
                         + (((u32)(ks * 32) + bkh) ^ ((u32)brow_l << 4));
                u32 b0, b1;
                ldmx2(vb + brel, b0, b1);
#pragma unroll
                for (int mt = 0; mt < 4; mt++)
                    mma16816(&acc[(mt * 8 + ct) * 4],
                             af[mt][0], af[mt][1], af[mt][2], af[mt][3], b0, b1);
            }
        }

        if (j + 1 < NTILES) scalarP(j + 1, buf ^ 1);
        asm volatile("cp.async.wait_group 0;" ::: "memory");
        __syncthreads();
    }

    // Row sums -> inverse
    rs[half * 128 + m] = lsum;
    __syncthreads();
    if (t < 128) rs[t] = 1.0f / (rs[t] + rs[t + 128]);
    __syncthreads();

    float gm = *gamma;

    // Epilogue: out[b,c,m] = gamma * acc * inv[m] + x[b,c,m]
#pragma unroll
    for (int mt = 0; mt < 4; mt++) {
        int r0 = m_blk + mt * 16 + (l >> 2);
        float s0 = gm * rs[r0];
        float s1 = gm * rs[r0 + 8];
#pragma unroll
        for (int ct = 0; ct < 8; ct++) {
            int c0 = c_blk + ct * 8 + (l & 3) * 2;
            const float* d = &acc[(mt * 8 + ct) * 4];
            size_t a0 = ((size_t)(b * NC + c0)) * NN + m0 + r0;
            size_t a1 = a0 + NN;
            out[a0]     = d[0] * s0 + x[a0];
            out[a1]     = d[1] * s0 + x[a1];
            out[a0 + 8] = d[2] * s1 + x[a0 + 8];
            out[a1 + 8] = d[3] * s1 + x[a1 + 8];
        }
    }
}

// ---------------------------------------------------------------------------
extern "C" void kernel_launch(void* const* d_in, const int* in_sizes, int n_in,
                              void* d_out, int out_size)
{
    const float* x     = (const float*)d_in[0];
    const float* wq    = (const float*)d_in[1];
    const float* bq    = (const float*)d_in[2];
    const float* wk    = (const float*)d_in[3];
    const float* bk    = (const float*)d_in[4];
    const float* wv    = (const float*)d_in[5];
    const float* bv    = (const float*)d_in[6];
    const float* gamma = (const float*)d_in[7];
    float* out = (float*)d_out;

    cudaFuncSetAttribute(flash_mma_kernel,
                         cudaFuncAttributeMaxDynamicSharedMemorySize,
                         FLASH_SMEM);

    qk_proj_kernel<<<dim3(NN / 256, NB), 256>>>(x, wq, bq, wk, bk);
    v_proj_kernel<<<dim3(NN / 64, NC / 64, NB), 256>>>(x, wv, bv);
    flash_mma_kernel<<<dim3(NN / BM, NB), 256, FLASH_SMEM>>>(x, gamma, out);
}

// round 7
// speedup vs baseline: 3.9652x; 1.2301x over previous
#include <cuda_runtime.h>
#include <cuda_bf16.h>
#include <cuda_fp16.h>
#include <cstdint>

// Problem constants
#define NB 8       // batch
#define NC 256     // channels
#define NN 4096    // H*W
#define ND 8       // d_qk
#define BM 128     // query rows per CTA
#define BN2 64     // key tile
#define NTILES (NN / BN2)
#define LOG2E 1.4426950408889634f

typedef unsigned long long u64;
typedef unsigned int u32;

// Scratch (device globals; allocation APIs are forbidden)
__device__ float g_q[NB * NN * ND];                   // [b][n][d]
__device__ float g_k[NB * NN * ND];                   // [b][n][d]
__device__ __nv_bfloat16 g_v[(size_t)NB * NC * NN];   // [b][c][n]

// ---------------- helpers ----------------
__device__ __forceinline__ u64 pk(float a, float b) {
    u64 r; asm("mov.b64 %0, {%1,%2};" : "=l"(r) : "f"(a), "f"(b)); return r;
}
__device__ __forceinline__ void fma2(u64 &d, u64 a, u64 b) {
    asm("fma.rn.f32x2 %0, %1, %2, %0;" : "+l"(d) : "l"(a), "l"(b));
}
__device__ __forceinline__ float2 unpk(u64 v) {
    float2 r; asm("mov.b64 {%0,%1}, %2;" : "=f"(r.x), "=f"(r.y) : "l"(v)); return r;
}
// pack bf16x2: lower 16 bits = first arg
__device__ __forceinline__ u32 bf2(float lo, float hi) {
    u32 r; asm("cvt.rn.bf16x2.f32 %0, %1, %2;" : "=r"(r) : "f"(hi), "f"(lo)); return r;
}
__device__ __forceinline__ float bflo(u32 w) { return __uint_as_float(w << 16); }
__device__ __forceinline__ float bfhi(u32 w) { return __uint_as_float(w & 0xffff0000u); }
__device__ __forceinline__ float ex2f(float x) {
    float r; asm("ex2.approx.f32 %0, %1;" : "=f"(r) : "f"(x)); return r;
}
__device__ __forceinline__ u32 smem_u32(const void* p) {
    u32 a; asm("{ .reg .u64 t; cvta.to.shared.u64 t, %1; cvt.u32.u64 %0, t; }" : "=r"(a) : "l"(p));
    return a;
}
__device__ __forceinline__ void cpa16(u32 dst, const void* src) {
    asm volatile("cp.async.cg.shared.global [%0], [%1], 16;" :: "r"(dst), "l"(src));
}
__device__ __forceinline__ void ldmx4(u32 a, u32 &r0, u32 &r1, u32 &r2, u32 &r3) {
    asm volatile("ldmatrix.sync.aligned.m8n8.x4.shared.b16 {%0,%1,%2,%3}, [%4];"
                 : "=r"(r0), "=r"(r1), "=r"(r2), "=r"(r3) : "r"(a));
}
__device__ __forceinline__ void ldmx2(u32 a, u32 &r0, u32 &r1) {
    asm volatile("ldmatrix.sync.aligned.m8n8.x2.shared.b16 {%0,%1}, [%2];"
                 : "=r"(r0), "=r"(r1) : "r"(a));
}
__device__ __forceinline__ void mma16816(float* d, u32 a0, u32 a1, u32 a2, u32 a3,
                                         u32 b0, u32 b1) {
    asm volatile(
        "mma.sync.aligned.m16n8k16.row.col.f32.bf16.bf16.f32 "
        "{%0,%1,%2,%3}, {%4,%5,%6,%7}, {%8,%9}, {%0,%1,%2,%3};"
        : "+f"(d[0]), "+f"(d[1]), "+f"(d[2]), "+f"(d[3])
        : "r"(a0), "r"(a1), "r"(a2), "r"(a3), "r"(b0), "r"(b1));
}

// ---------------------------------------------------------------------------
// Kernel 1: Q/K projections. 64-thread CTAs for occupancy (512 blocks).
// ---------------------------------------------------------------------------
__global__ __launch_bounds__(64) void qk_proj_kernel(
    const float* __restrict__ x,
    const float* __restrict__ wq, const float* __restrict__ bq,
    const float* __restrict__ wk, const float* __restrict__ bk)
{
    __shared__ float swq[ND * NC];
    __shared__ float swk[ND * NC];
    int t = threadIdx.x;
    for (int i = t; i < ND * NC; i += 64) { swq[i] = wq[i]; swk[i] = wk[i]; }
    __syncthreads();

    int b = blockIdx.y;
    int n = blockIdx.x * 64 + t;
    const float* xp = x + (size_t)b * NC * NN + n;

    float qa[ND], ka[ND];
#pragma unroll
    for (int d = 0; d < ND; d++) { qa[d] = bq[d]; ka[d] = bk[d]; }

#pragma unroll 4
    for (int c = 0; c < NC; c++) {
        float xv = xp[(size_t)c * NN];
#pragma unroll
        for (int d = 0; d < ND; d++) {
            qa[d] = fmaf(swq[d * NC + c], xv, qa[d]);
            ka[d] = fmaf(swk[d * NC + c], xv, ka[d]);
        }
    }
    size_t base = ((size_t)b * NN + n) * ND;
#pragma unroll
    for (int d = 0; d < ND; d++) { g_q[base + d] = qa[d]; g_k[base + d] = ka[d]; }
}

// ---------------------------------------------------------------------------
// Kernel 2: V projection -> bf16 in natural [b][c][n] layout.
// ---------------------------------------------------------------------------
__global__ __launch_bounds__(256) void v_proj_kernel(
    const float* __restrict__ x,
    const float* __restrict__ wv, const float* __restrict__ bv)
{
    __shared__ float Xs[16][64];  // [c][n]
    __shared__ float Ws[16][64];  // [c][co]

    int t   = threadIdx.x;
    int nb_ = blockIdx.x * 64;
    int cb  = blockIdx.y * 64;
    int b   = blockIdx.z;

    int tn  = t & 15;
    int tco = t >> 4;

    u64 acc[4][2];
#pragma unroll
    for (int i = 0; i < 4; i++) { acc[i][0] = 0ULL; acc[i][1] = 0ULL; }

    for (int c0 = 0; c0 < NC; c0 += 16) {
#pragma unroll
        for (int e = 0; e < 4; e++) {
            int lin = t + 256 * e;
            int cl = lin >> 6, nl = lin & 63;
            Xs[cl][nl] = x[((size_t)b * NC + c0 + cl) * NN + nb_ + nl];
        }
#pragma unroll
        for (int e = 0; e < 4; e++) {
            int col = t & 63;
            int cl  = (t >> 6) + 4 * e;
            Ws[cl][col] = wv[(size_t)(cb + col) * NC + c0 + cl];
        }
        __syncthreads();

#pragma unroll
        for (int c = 0; c < 16; c++) {
            float4 xv = *(const float4*)&Xs[c][tn * 4];
            float4 wv4 = *(const float4*)&Ws[c][tco * 4];
            u64 w01 = pk(wv4.x, wv4.y);
            u64 w23 = pk(wv4.z, wv4.w);
            float xs[4] = {xv.x, xv.y, xv.z, xv.w};
#pragma unroll
            for (int i = 0; i < 4; i++) {
                u64 xp2 = pk(xs[i], xs[i]);
                fma2(acc[i][0], xp2, w01);
                fma2(acc[i][1], xp2, w23);
            }
        }
        __syncthreads();
    }

    float bvv[4];
#pragma unroll
    for (int j = 0; j < 4; j++) bvv[j] = bv[cb + tco * 4 + j];

    float vals[4][4];
#pragma unroll
    for (int i = 0; i < 4; i++) {
        float2 a0 = unpk(acc[i][0]);
        float2 a1 = unpk(acc[i][1]);
        vals[i][0] = a0.x + bvv[0];
        vals[i][1] = a0.y + bvv[1];
        vals[i][2] = a1.x + bvv[2];
        vals[i][3] = a1.y + bvv[3];
    }
#pragma unroll
    for (int jc = 0; jc < 4; jc++) {
        u32 w0 = bf2(vals[0][jc], vals[1][jc]);
        u32 w1 = bf2(vals[2][jc], vals[3][jc]);
        size_t e = ((size_t)b * NC + cb + tco * 4 + jc) * NN + nb_ + tn * 4;
        *(uint2*)((void*)(g_v + e)) = make_uint2(w0, w1);
    }
}

// ---------------------------------------------------------------------------
// Kernel 3: flash attention, all-bf16 HMMA, no max pass.
//  - S = Q·K via MMA: Q held as hi/lo bf16 A-fragments (exact to ~2^-16),
//    K per-tile in smem as [n][Khi(16B)|Klo(16B)] swizzled; B=[Khi|Khi] then
//    [Klo|Klo] -> s = Q·Khi + Q·Klo.
//  - P = ex2(s) packed bf16 into smem (ldmatrix layout); row sums use the
//    ROUNDED values so normalization cancels P quantization.
//  - P·V: R5-proven ldmx4/ldmx2 + m16n8k16 block, single bf16 V plane.
//  - Pipeline: K via register staging (single buffer), V cp.async double
//    buffer, 2 barriers/tile.
// Warps: S-phase strip = rows w*16..+15; PV m_blk=(w>>2)*64, c_blk=(w&3)*64.
// ---------------------------------------------------------------------------
#define OFF_K   0                     // [64][32] bf16 hi/lo = 2048 B
#define OFF_P   2048                  // [128][64] bf16 (128B rows) = 16384 B
#define OFF_V   18432                 // 2 x [256][64] bf16 = 65536 B
#define OFF_RS  83968                 // 256 f32 = 1024 B
#define FLASH_SMEM 84992

__global__ __launch_bounds__(256, 1) void flash_mma_kernel(
    const float* __restrict__ x,
    const float* __restrict__ gamma,
    float* __restrict__ out)
{
    extern __shared__ char sm[];
    u32 sb = smem_u32(sm);
    int t = threadIdx.x, l = t & 31, w = t >> 5;
    int b = blockIdx.y, m0 = blockIdx.x * BM;
    int m_blk = (w >> 2) * 64, c_blk = (w & 3) * 64;
    int r = l >> 2, c2 = (l & 3) * 2;

    // ---- Q fragments: hi/lo bf16, log2e folded ----
    u32 qa0, qa1, qa2, qa3;
    {
        int qrow = m0 + w * 16 + r;
        const float* qp = g_q + ((size_t)b * NN + qrow) * ND + c2;
        const float* qp2 = qp + 8 * ND;
        float x0 = qp[0] * LOG2E, x1 = qp[1] * LOG2E;
        float y0 = qp2[0] * LOG2E, y1 = qp2[1] * LOG2E;
        qa0 = bf2(x0, x1);
        qa1 = bf2(y0, y1);
        qa2 = bf2(x0 - bflo(qa0), x1 - bfhi(qa0));
        qa3 = bf2(y0 - bflo(qa1), y1 - bfhi(qa1));
    }

    float acc[128];
#pragma unroll
    for (int i = 0; i < 128; i++) acc[i] = 0.0f;
    float lsA = 0.0f, lsB = 0.0f;

    const __nv_bfloat16* vg = g_v + (size_t)b * NC * NN;

    // per-lane PV ldmatrix address components (R5-proven)
    u32 pbase = sb + OFF_P, vbase = sb + OFF_V;
    int arow  = m_blk + (l & 15);
    u32 aswz  = (u32)((l & 7) << 4);
    u32 acolh = (u32)((l >> 4) << 4);
    int brow_l = l & 7;
    u32 bkh   = (u32)(((l >> 3) & 1) << 4);

    float4 kA, kB;  // K register staging (threads 0..63)

    auto ldgK = [&](int j) {
        if (t < 64) {
            const float4* kp = (const float4*)(g_k + ((size_t)b * NN + j * BN2 + t) * ND);
            kA = kp[0]; kB = kp[1];
        }
    };
    auto stsK = [&]() {
        if (t < 64) {
            uint4 hi, lo;
            hi.x = bf2(kA.x, kA.y); hi.y = bf2(kA.z, kA.w);
            hi.z = bf2(kB.x, kB.y); hi.w = bf2(kB.z, kB.w);
            lo.x = bf2(kA.x - bflo(hi.x), kA.y - bfhi(hi.x));
            lo.y = bf2(kA.z - bflo(hi.y), kA.w - bfhi(hi.y));
            lo.z = bf2(kB.x - bflo(hi.z), kB.y - bfhi(hi.z));
            lo.w = bf2(kB.z - bflo(hi.w), kB.w - bfhi(hi.w));
            u32 sw = (u32)((t & 4) << 2);
            *(uint4*)(sm + OFF_K + t * 32 + sw) = hi;
            *(uint4*)(sm + OFF_K + t * 32 + (16u ^ sw)) = lo;
        }
    };
    auto loadV = [&](int j, int buf) {
        u32 vd = vbase + (u32)buf * 32768;
        const __nv_bfloat16* vsrc = vg + j * BN2;
#pragma unroll
        for (int e = 0; e < 8; e++) {
            int lin = e * 256 + t;
            int row = lin >> 3, c16 = lin & 7;
            u32 dof = (u32)(row * 128 + ((c16 * 16) ^ ((row & 7) << 4)));
            cpa16(vd + dof, vsrc + (size_t)row * NN + c16 * 8);
        }
        asm volatile("cp.async.commit_group;" ::: "memory");
    };
    // S phase: MMA S, exp, pack, store P, accumulate rounded row sums
    auto sphase = [&]() {
        int rowa = w * 16 + r;
        u32 paxor = (u32)((rowa & 7) << 4);
        u32 pcol  = (u32)((l & 3) * 4);
        char* prow0 = sm + OFF_P + rowa * 128;
        char* prow8 = prow0 + 8 * 128;
#pragma unroll
        for (int nt = 0; nt < 8; nt++) {
            u32 krow = (u32)(nt * 8 + (l & 7));
            u32 ksw  = (krow & 4) << 2;
            u32 ka   = sb + OFF_K + krow * 32;
            u32 bh0, bh1, bl0, bl1;
            ldmx2(ka + ksw, bh0, bh1);
            ldmx2(ka + (16u ^ ksw), bl0, bl1);
            float ds[4] = {0.f, 0.f, 0.f, 0.f};
            mma16816(ds, qa0, qa1, qa2, qa3, bh0, bh1);
            mma16816(ds, qa0, qa1, qa2, qa3, bl0, bl1);
            u32 p01 = bf2(ex2f(ds[0]), ex2f(ds[1]));
            u32 p23 = bf2(ex2f(ds[2]), ex2f(ds[3]));
            lsA += bflo(p01) + bfhi(p01);
            lsB += bflo(p23) + bfhi(p23);
            u32 cbyte = ((u32)(nt * 16) + pcol) ^ paxor;
            *(u32*)(prow0 + cbyte) = p01;
            *(u32*)(prow8 + cbyte) = p23;
        }
    };

    // ---- prologue ----
    ldgK(0); stsK(); loadV(0, 0);
    asm volatile("cp.async.wait_group 0;" ::: "memory");
    __syncthreads();

    for (int j = 0; j < NTILES; j++) {
        int buf = j & 1;
        sphase();
        if (j + 1 < NTILES) { ldgK(j + 1); loadV(j + 1, buf ^ 1); }
        __syncthreads();                 // P(j) visible; K(j) reads done
        if (j + 1 < NTILES) stsK();

        // ---- PV MMA(j) ----
        u32 vb = vbase + (u32)buf * 32768;
#pragma unroll
        for (int ks = 0; ks < 4; ks++) {
            u32 af[4][4];
#pragma unroll
            for (int mt = 0; mt < 4; mt++) {
                u32 ad = pbase + (u32)((arow + mt * 16) * 128)
                       + (((u32)(ks * 32) + acolh) ^ aswz);
                ldmx4(ad, af[mt][0], af[mt][1], af[mt][2], af[mt][3]);
            }
#pragma unroll
            for (int ct = 0; ct < 8; ct++) {
                u32 brel = (u32)((c_blk + ct * 8 + brow_l) * 128)
                         + (((u32)(ks * 32) + bkh) ^ ((u32)brow_l << 4));
                u32 b0, b1;
                ldmx2(vb + brel, b0, b1);
#pragma unroll
                for (int mt = 0; mt < 4; mt++)
                    mma16816(&acc[(mt * 8 + ct) * 4],
                             af[mt][0], af[mt][1], af[mt][2], af[mt][3], b0, b1);
            }
        }

        asm volatile("cp.async.wait_group 0;" ::: "memory");
        __syncthreads();                 // V(j+1), K(j+1) visible; P free
    }

    // ---- row sums (reduce over lane quads) ----
    lsA += __shfl_xor_sync(0xffffffffu, lsA, 1);
    lsA += __shfl_xor_sync(0xffffffffu, lsA, 2);
    lsB += __shfl_xor_sync(0xffffffffu, lsB, 1);
    lsB += __shfl_xor_sync(0xffffffffu, lsB, 2);
    float* rs = (float*)(sm + OFF_RS);
    if ((l & 3) == 0) {
        rs[w * 16 + r]     = lsA;
        rs[w * 16 + r + 8] = lsB;
    }
    __syncthreads();
    if (t < 128) rs[t] = 1.0f / rs[t];
    __syncthreads();

    float gm = *gamma;

    // ---- Epilogue: out[b,c,m] = gamma * acc * inv[m] + x[b,c,m] ----
#pragma unroll
    for (int mt = 0; mt < 4; mt++) {
        int r0 = m_blk + mt * 16 + (l >> 2);
        float s0 = gm * rs[r0];
        float s1 = gm * rs[r0 + 8];
#pragma unroll
        for (int ct = 0; ct < 8; ct++) {
            int c0 = c_blk + ct * 8 + (l & 3) * 2;
            const float* d = &acc[(mt * 8 + ct) * 4];
            size_t a0 = ((size_t)(b * NC + c0)) * NN + m0 + r0;
            size_t a1 = a0 + NN;
            out[a0]     = d[0] * s0 + x[a0];
            out[a1]     = d[1] * s0 + x[a1];
            out[a0 + 8] = d[2] * s1 + x[a0 + 8];
            out[a1 + 8] = d[3] * s1 + x[a1 + 8];
        }
    }
}

// ---------------------------------------------------------------------------
extern "C" void kernel_launch(void* const* d_in, const int* in_sizes, int n_in,
                              void* d_out, int out_size)
{
    const float* x     = (const float*)d_in[0];
    const float* wq    = (const float*)d_in[1];
    const float* bq    = (const float*)d_in[2];
    const float* wk    = (const float*)d_in[3];
    const float* bk    = (const float*)d_in[4];
    const float* wv    = (const float*)d_in[5];
    const float* bv    = (const float*)d_in[6];
    const float* gamma = (const float*)d_in[7];
    float* out = (float*)d_out;

    cudaFuncSetAttribute(flash_mma_kernel,
                         cudaFuncAttributeMaxDynamicSharedMemorySize,
                         FLASH_SMEM);

    qk_proj_kernel<<<dim3(NN / 64, NB), 64>>>(x, wq, bq, wk, bk);
    v_proj_kernel<<<dim3(NN / 64, NC / 64, NB), 256>>>(x, wv, bv);
    flash_mma_kernel<<<dim3(NN / BM, NB), 256, FLASH_SMEM>>>(x, gamma, out);
}

// round 8
// speedup vs baseline: 6.8036x; 1.7158x over previous
#include <cuda_runtime.h>
#include <cuda_bf16.h>
#include <cuda_fp16.h>
#include <cstdint>

// Problem constants
#define NB 8       // batch
#define NC 256     // channels
#define NN 4096    // H*W
#define ND 8       // d_qk
#define BM 128     // query rows per CTA (flash)
#define BN2 64     // key tile
#define NTILES (NN / BN2)
#define LOG2E 1.4426950408889634f

typedef unsigned long long u64;
typedef unsigned int u32;

// Scratch (device globals; allocation APIs are forbidden)
__device__ float g_q[NB * NN * ND];                   // [b][n][d]
__device__ float g_k[NB * NN * ND];                   // [b][n][d]
__device__ __nv_bfloat16 g_v[(size_t)NB * NC * NN];   // [b][c][n]

// ---------------- helpers ----------------
// pack bf16x2: lower 16 bits = first arg
__device__ __forceinline__ u32 bf2(float lo, float hi) {
    u32 r; asm("cvt.rn.bf16x2.f32 %0, %1, %2;" : "=r"(r) : "f"(hi), "f"(lo)); return r;
}
__device__ __forceinline__ float bflo(u32 w) { return __uint_as_float(w << 16); }
__device__ __forceinline__ float bfhi(u32 w) { return __uint_as_float(w & 0xffff0000u); }
__device__ __forceinline__ float ex2f(float x) {
    float r; asm("ex2.approx.f32 %0, %1;" : "=f"(r) : "f"(x)); return r;
}
__device__ __forceinline__ u32 smem_u32(const void* p) {
    u32 a; asm("{ .reg .u64 t; cvta.to.shared.u64 t, %1; cvt.u32.u64 %0, t; }" : "=r"(a) : "l"(p));
    return a;
}
__device__ __forceinline__ void cpa16(u32 dst, const void* src) {
    asm volatile("cp.async.cg.shared.global [%0], [%1], 16;" :: "r"(dst), "l"(src));
}
__device__ __forceinline__ void ldmx4(u32 a, u32 &r0, u32 &r1, u32 &r2, u32 &r3) {
    asm volatile("ldmatrix.sync.aligned.m8n8.x4.shared.b16 {%0,%1,%2,%3}, [%4];"
                 : "=r"(r0), "=r"(r1), "=r"(r2), "=r"(r3) : "r"(a));
}
__device__ __forceinline__ void ldmx2(u32 a, u32 &r0, u32 &r1) {
    asm volatile("ldmatrix.sync.aligned.m8n8.x2.shared.b16 {%0,%1}, [%2];"
                 : "=r"(r0), "=r"(r1) : "r"(a));
}
__device__ __forceinline__ void ldmx2t(u32 a, u32 &r0, u32 &r1) {
    asm volatile("ldmatrix.sync.aligned.m8n8.x2.trans.shared.b16 {%0,%1}, [%2];"
                 : "=r"(r0), "=r"(r1) : "r"(a));
}
__device__ __forceinline__ void mma16816(float* d, u32 a0, u32 a1, u32 a2, u32 a3,
                                         u32 b0, u32 b1) {
    asm volatile(
        "mma.sync.aligned.m16n8k16.row.col.f32.bf16.bf16.f32 "
        "{%0,%1,%2,%3}, {%4,%5,%6,%7}, {%8,%9}, {%0,%1,%2,%3};"
        : "+f"(d[0]), "+f"(d[1]), "+f"(d[2]), "+f"(d[3])
        : "r"(a0), "r"(a1), "r"(a2), "r"(a3), "r"(b0), "r"(b1));
}

// ---------------------------------------------------------------------------
// Kernel 1 (fused): V projection + Q/K projection via HMMA.
// W' = [wv(256); wq(8); wk(8)] rows, hi/lo bf16. X tile [ci][n] bf16 hi/lo.
// CTA: batch b, n-tile 128, full co 256 + 16 qk rows. 4 ci-chunks of 64.
// Warp w: co_blk=(w&3)*64, n_blk=(w>>2)*64; plus qk n-tiles {2w, 2w+1}.
// ---------------------------------------------------------------------------
#define PW_H   0                      // [272][64] bf16 = 34816 B
#define PW_L   34816                  // [272][64] bf16
#define PX_H   69632                  // [64][128] bf16 = 16384 B
#define PX_L   86016                  // [64][128] bf16
#define PBV    102400                 // 256 f32 = 1024 B
#define PROJ_SMEM 103424
#define PSTAGE 0                      // epilogue stage reuses W area (64 KB)

__global__ __launch_bounds__(256, 1) void proj_kernel(
    const float* __restrict__ x,
    const float* __restrict__ wq, const float* __restrict__ bq,
    const float* __restrict__ wk, const float* __restrict__ bk,
    const float* __restrict__ wv, const float* __restrict__ bv)
{
    extern __shared__ char sm[];
    u32 sb = smem_u32(sm);
    int t = threadIdx.x, l = t & 31, w = t >> 5;
    int b = blockIdx.y, n0 = blockIdx.x * 128;
    int co_blk = (w & 3) * 64, n_blk = (w >> 2) * 64;

    float* sBV = (float*)(sm + PBV);
    if (t < 256) sBV[t] = bv[t];

    float acc[128];
#pragma unroll
    for (int i = 0; i < 128; i++) acc[i] = 0.0f;
    float qacc[2][4];
#pragma unroll
    for (int i = 0; i < 2; i++)
#pragma unroll
        for (int jj = 0; jj < 4; jj++) qacc[i][jj] = 0.0f;

    // per-lane A addresses (flash-proven mapping)
    int arow = co_blk + (l & 15);
    int qrow = 256 + (l & 15);
    u32 acolh = (u32)((l >> 4) << 4);

    for (int ch = 0; ch < 4; ch++) {
        int c0 = ch * 64;
        // ---- load W' chunk (272 rows x 64 ci fp32) -> hi/lo bf16 smem ----
#pragma unroll
        for (int e = 0; e < 17; e++) {
            int i = t + 256 * e;
            int row = i >> 4, f4 = i & 15;
            const float* src;
            if (row < 256)      src = wv + (size_t)row * NC + c0;
            else if (row < 264) src = wq + (size_t)(row - 256) * NC + c0;
            else                src = wk + (size_t)(row - 264) * NC + c0;
            float4 v4 = *(const float4*)(src + f4 * 4);
            u32 h0 = bf2(v4.x, v4.y), h1 = bf2(v4.z, v4.w);
            u32 l0 = bf2(v4.x - bflo(h0), v4.y - bfhi(h0));
            u32 l1 = bf2(v4.z - bflo(h1), v4.w - bfhi(h1));
            u32 off = (u32)(row * 128) + (u32)((f4 * 8) ^ ((row & 7) << 4));
            *(uint2*)(sm + PW_H + off) = make_uint2(h0, h1);
            *(uint2*)(sm + PW_L + off) = make_uint2(l0, l1);
        }
        // ---- load X chunk (64 ci x 128 n fp32) -> hi/lo bf16 smem [ci][n] ----
#pragma unroll
        for (int e = 0; e < 8; e++) {
            int i = t + 256 * e;
            int row = i >> 5, n4 = (i & 31) * 4;
            float4 v4 = *(const float4*)(x + ((size_t)b * NC + c0 + row) * NN + n0 + n4);
            u32 h0 = bf2(v4.x, v4.y), h1 = bf2(v4.z, v4.w);
            u32 l0 = bf2(v4.x - bflo(h0), v4.y - bfhi(h0));
            u32 l1 = bf2(v4.z - bflo(h1), v4.w - bfhi(h1));
            u32 off = (u32)(row * 256) + (u32)((n4 * 2) ^ ((row & 7) << 4));
            *(uint2*)(sm + PX_H + off) = make_uint2(h0, h1);
            *(uint2*)(sm + PX_L + off) = make_uint2(l0, l1);
        }
        __syncthreads();

        // ---- MMA over this chunk ----
#pragma unroll
        for (int kt = 0; kt < 4; kt++) {
            u32 kb = (u32)(kt * 32);
            // A fragments: W hi/lo, 4 m-tiles of the warp's co block
            u32 ah[4][4], al[4][4];
#pragma unroll
            for (int mt = 0; mt < 4; mt++) {
                int rr = arow + mt * 16;
                u32 ad = (u32)(rr * 128) + ((kb + acolh) ^ (u32)((rr & 7) << 4));
                ldmx4(sb + PW_H + ad, ah[mt][0], ah[mt][1], ah[mt][2], ah[mt][3]);
                ldmx4(sb + PW_L + ad, al[mt][0], al[mt][1], al[mt][2], al[mt][3]);
            }
            // B fragments: X hi (trans from [ci][n]); V rows use hi only
#pragma unroll
            for (int nt = 0; nt < 8; nt++) {
                int cir = kt * 16 + (l & 15);
                u32 bd = sb + PX_H + (u32)(cir * 256)
                       + (u32)(((n_blk + nt * 8) * 2) ^ ((cir & 7) << 4));
                u32 b0, b1;
                ldmx2t(bd, b0, b1);
#pragma unroll
                for (int mt = 0; mt < 4; mt++) {
                    float* d = &acc[(mt * 8 + nt) * 4];
                    mma16816(d, ah[mt][0], ah[mt][1], ah[mt][2], ah[mt][3], b0, b1);
                    mma16816(d, al[mt][0], al[mt][1], al[mt][2], al[mt][3], b0, b1);
                }
            }
            // qk rows: 3-plane (Whi*Xhi + Whi*Xlo + Wlo*Xhi), n-tiles 2w,2w+1
            {
                int rr = qrow;
                u32 ad = (u32)(rr * 128) + ((kb + acolh) ^ (u32)((rr & 7) << 4));
                u32 qh[4], ql[4];
                ldmx4(sb + PW_H + ad, qh[0], qh[1], qh[2], qh[3]);
                ldmx4(sb + PW_L + ad, ql[0], ql[1], ql[2], ql[3]);
                int cir = kt * 16 + (l & 15);
                u32 rswz = (u32)((cir & 7) << 4);
                u32 rbase = (u32)(cir * 256);
#pragma unroll
                for (int qi = 0; qi < 2; qi++) {
                    int qnt = 2 * w + qi;
                    u32 cbyte = (u32)((qnt * 8) * 2) ^ rswz;
                    u32 bh0, bh1, bl0, bl1;
                    ldmx2t(sb + PX_H + rbase + cbyte, bh0, bh1);
                    ldmx2t(sb + PX_L + rbase + cbyte, bl0, bl1);
                    mma16816(qacc[qi], qh[0], qh[1], qh[2], qh[3], bh0, bh1);
                    mma16816(qacc[qi], qh[0], qh[1], qh[2], qh[3], bl0, bl1);
                    mma16816(qacc[qi], ql[0], ql[1], ql[2], ql[3], bh0, bh1);
                }
            }
        }
        __syncthreads();
    }

    // ---- qk epilogue: fp32 with bias -> g_q/g_k  [b][n][d] ----
    {
        int d_ = l >> 2;
        float bq_ = bq[d_], bk_ = bk[d_];
#pragma unroll
        for (int qi = 0; qi < 2; qi++) {
            int n_g = n0 + (2 * w + qi) * 8 + (l & 3) * 2;
            size_t e0 = ((size_t)b * NN + n_g) * ND + d_;
            g_q[e0]      = qacc[qi][0] + bq_;
            g_q[e0 + ND] = qacc[qi][1] + bq_;
            g_k[e0]      = qacc[qi][2] + bk_;
            g_k[e0 + ND] = qacc[qi][3] + bk_;
        }
    }

    // ---- V epilogue: acc + bv -> bf16 via smem stage -> coalesced g_v ----
    {
        char* stg = sm + PSTAGE + w * 8192;  // [64 co][64 n] bf16, swizzled
#pragma unroll
        for (int mt = 0; mt < 4; mt++) {
            int r0 = mt * 16 + (l >> 2);
            float b0_ = sBV[co_blk + r0];
            float b1_ = sBV[co_blk + r0 + 8];
#pragma unroll
            for (int nt = 0; nt < 8; nt++) {
                const float* d = &acc[(mt * 8 + nt) * 4];
                u32 w0 = bf2(d[0] + b0_, d[1] + b0_);
                u32 w1 = bf2(d[2] + b1_, d[3] + b1_);
                u32 cb = (u32)(nt * 16 + (l & 3) * 4);
                *(u32*)(stg + r0 * 128 + (cb ^ ((r0 & 7) << 4))) = w0;
                *(u32*)(stg + (r0 + 8) * 128 + (cb ^ (((r0 + 8) & 7) << 4))) = w1;
            }
        }
    }
    __syncthreads();
    // copy stage -> g_v (16B chunks, coalesced over n)
#pragma unroll
    for (int e = 0; e < 16; e++) {
        int i = t + 256 * e;
        int co = i >> 4, chn = i & 15;
        int n = chn * 8;
        int wr = (co >> 6) | ((n >> 6) << 2);
        int cr = co & 63, nr = n & 63;
        float4 v4 = *(const float4*)(sm + PSTAGE + wr * 8192 + cr * 128
                                     + ((nr * 2) ^ ((cr & 7) << 4)));
        *(float4*)((void*)(g_v + ((size_t)b * NC + co) * NN + n0 + n)) = v4;
    }
}

// ---------------------------------------------------------------------------
// Kernel 2: flash attention (unchanged from passing R6 version).
// ---------------------------------------------------------------------------
#define OFF_K   0                     // [64][32] bf16 hi/lo = 2048 B
#define OFF_P   2048                  // [128][64] bf16 (128B rows) = 16384 B
#define OFF_V   18432                 // 2 x [256][64] bf16 = 65536 B
#define OFF_RS  83968                 // 256 f32 = 1024 B
#define FLASH_SMEM 84992

__global__ __launch_bounds__(256, 1) void flash_mma_kernel(
    const float* __restrict__ x,
    const float* __restrict__ gamma,
    float* __restrict__ out)
{
    extern __shared__ char sm[];
    u32 sb = smem_u32(sm);
    int t = threadIdx.x, l = t & 31, w = t >> 5;
    int b = blockIdx.y, m0 = blockIdx.x * BM;
    int m_blk = (w >> 2) * 64, c_blk = (w & 3) * 64;
    int r = l >> 2, c2 = (l & 3) * 2;

    // ---- Q fragments: hi/lo bf16, log2e folded ----
    u32 qa0, qa1, qa2, qa3;
    {
        int qrow = m0 + w * 16 + r;
        const float* qp = g_q + ((size_t)b * NN + qrow) * ND + c2;
        const float* qp2 = qp + 8 * ND;
        float x0 = qp[0] * LOG2E, x1 = qp[1] * LOG2E;
        float y0 = qp2[0] * LOG2E, y1 = qp2[1] * LOG2E;
        qa0 = bf2(x0, x1);
        qa1 = bf2(y0, y1);
        qa2 = bf2(x0 - bflo(qa0), x1 - bfhi(qa0));
        qa3 = bf2(y0 - bflo(qa1), y1 - bfhi(qa1));
    }

    float acc[128];
#pragma unroll
    for (int i = 0; i < 128; i++) acc[i] = 0.0f;
    float lsA = 0.0f, lsB = 0.0f;

    const __nv_bfloat16* vg = g_v + (size_t)b * NC * NN;

    u32 pbase = sb + OFF_P, vbase = sb + OFF_V;
    int arow  = m_blk + (l & 15);
    u32 aswz  = (u32)((l & 7) << 4);
    u32 acolh = (u32)((l >> 4) << 4);
    int brow_l = l & 7;
    u32 bkh   = (u32)(((l >> 3) & 1) << 4);

    float4 kA, kB;  // K register staging (threads 0..63)

    auto ldgK = [&](int j) {
        if (t < 64) {
            const float4* kp = (const float4*)(g_k + ((size_t)b * NN + j * BN2 + t) * ND);
            kA = kp[0]; kB = kp[1];
        }
    };
    auto stsK = [&]() {
        if (t < 64) {
            uint4 hi, lo;
            hi.x = bf2(kA.x, kA.y); hi.y = bf2(kA.z, kA.w);
            hi.z = bf2(kB.x, kB.y); hi.w = bf2(kB.z, kB.w);
            lo.x = bf2(kA.x - bflo(hi.x), kA.y - bfhi(hi.x));
            lo.y = bf2(kA.z - bflo(hi.y), kA.w - bfhi(hi.y));
            lo.z = bf2(kB.x - bflo(hi.z), kB.y - bfhi(hi.z));
            lo.w = bf2(kB.z - bflo(hi.w), kB.w - bfhi(hi.w));
            u32 sw = (u32)((t & 4) << 2);
            *(uint4*)(sm + OFF_K + t * 32 + sw) = hi;
            *(uint4*)(sm + OFF_K + t * 32 + (16u ^ sw)) = lo;
        }
    };
    auto loadV = [&](int j, int buf) {
        u32 vd = vbase + (u32)buf * 32768;
        const __nv_bfloat16* vsrc = vg + j * BN2;
#pragma unroll
        for (int e = 0; e < 8; e++) {
            int lin = e * 256 + t;
            int row = lin >> 3, c16 = lin & 7;
            u32 dof = (u32)(row * 128 + ((c16 * 16) ^ ((row & 7) << 4)));
            cpa16(vd + dof, vsrc + (size_t)row * NN + c16 * 8);
        }
        asm volatile("cp.async.commit_group;" ::: "memory");
    };
    auto sphase = [&]() {
        int rowa = w * 16 + r;
        u32 paxor = (u32)((rowa & 7) << 4);
        u32 pcol  = (u32)((l & 3) * 4);
        char* prow0 = sm + OFF_P + rowa * 128;
        char* prow8 = prow0 + 8 * 128;
#pragma unroll
        for (int nt = 0; nt < 8; nt++) {
            u32 krow = (u32)(nt * 8 + (l & 7));
            u32 ksw  = (krow & 4) << 2;
            u32 ka   = sb + OFF_K + krow * 32;
            u32 bh0, bh1, bl0, bl1;
            ldmx2(ka + ksw, bh0, bh1);
            ldmx2(ka + (16u ^ ksw), bl0, bl1);
            float ds[4] = {0.f, 0.f, 0.f, 0.f};
            mma16816(ds, qa0, qa1, qa2, qa3, bh0, bh1);
            mma16816(ds, qa0, qa1, qa2, qa3, bl0, bl1);
            u32 p01 = bf2(ex2f(ds[0]), ex2f(ds[1]));
            u32 p23 = bf2(ex2f(ds[2]), ex2f(ds[3]));
            lsA += bflo(p01) + bfhi(p01);
            lsB += bflo(p23) + bfhi(p23);
            u32 cbyte = ((u32)(nt * 16) + pcol) ^ paxor;
            *(u32*)(prow0 + cbyte) = p01;
            *(u32*)(prow8 + cbyte) = p23;
        }
    };

    // ---- prologue ----
    ldgK(0); stsK(); loadV(0, 0);
    asm volatile("cp.async.wait_group 0;" ::: "memory");
    __syncthreads();

    for (int j = 0; j < NTILES; j++) {
        int buf = j & 1;
        sphase();
        if (j + 1 < NTILES) { ldgK(j + 1); loadV(j + 1, buf ^ 1); }
        __syncthreads();
        if (j + 1 < NTILES) stsK();

        u32 vb = vbase + (u32)buf * 32768;
#pragma unroll
        for (int ks = 0; ks < 4; ks++) {
            u32 af[4][4];
#pragma unroll
            for (int mt = 0; mt < 4; mt++) {
                u32 ad = pbase + (u32)((arow + mt * 16) * 128)
                       + (((u32)(ks * 32) + acolh) ^ aswz);
                ldmx4(ad, af[mt][0], af[mt][1], af[mt][2], af[mt][3]);
            }
#pragma unroll
            for (int ct = 0; ct < 8; ct++) {
                u32 brel = (u32)((c_blk + ct * 8 + brow_l) * 128)
                         + (((u32)(ks * 32) + bkh) ^ ((u32)brow_l << 4));
                u32 b0, b1;
                ldmx2(vb + brel, b0, b1);
#pragma unroll
                for (int mt = 0; mt < 4; mt++)
                    mma16816(&acc[(mt * 8 + ct) * 4],
                             af[mt][0], af[mt][1], af[mt][2], af[mt][3], b0, b1);
            }
        }

        asm volatile("cp.async.wait_group 0;" ::: "memory");
        __syncthreads();
    }

    lsA += __shfl_xor_sync(0xffffffffu, lsA, 1);
    lsA += __shfl_xor_sync(0xffffffffu, lsA, 2);
    lsB += __shfl_xor_sync(0xffffffffu, lsB, 1);
    lsB += __shfl_xor_sync(0xffffffffu, lsB, 2);
    float* rs = (float*)(sm + OFF_RS);
    if ((l & 3) == 0) {
        rs[w * 16 + r]     = lsA;
        rs[w * 16 + r + 8] = lsB;
    }
    __syncthreads();
    if (t < 128) rs[t] = 1.0f / rs[t];
    __syncthreads();

    float gm = *gamma;

#pragma unroll
    for (int mt = 0; mt < 4; mt++) {
        int r0 = m_blk + mt * 16 + (l >> 2);
        float s0 = gm * rs[r0];
        float s1 = gm * rs[r0 + 8];
#pragma unroll
        for (int ct = 0; ct < 8; ct++) {
            int c0 = c_blk + ct * 8 + (l & 3) * 2;
            const float* d = &acc[(mt * 8 + ct) * 4];
            size_t a0 = ((size_t)(b * NC + c0)) * NN + m0 + r0;
            size_t a1 = a0 + NN;
            out[a0]     = d[0] * s0 + x[a0];
            out[a1]     = d[1] * s0 + x[a1];
            out[a0 + 8] = d[2] * s1 + x[a0 + 8];
            out[a1 + 8] = d[3] * s1 + x[a1 + 8];
        }
    }
}

// ---------------------------------------------------------------------------
extern "C" void kernel_launch(void* const* d_in, const int* in_sizes, int n_in,
                              void* d_out, int out_size)
{
    const float* x     = (const float*)d_in[0];
    const float* wq    = (const float*)d_in[1];
    const float* bq    = (const float*)d_in[2];
    const float* wk    = (const float*)d_in[3];
    const float* bk    = (const float*)d_in[4];
    const float* wv    = (const float*)d_in[5];
    const float* bv    = (const float*)d_in[6];
    const float* gamma = (const float*)d_in[7];
    float* out = (float*)d_out;

    cudaFuncSetAttribute(proj_kernel,
                         cudaFuncAttributeMaxDynamicSharedMemorySize,
                         PROJ_SMEM);
    cudaFuncSetAttribute(flash_mma_kernel,
                         cudaFuncAttributeMaxDynamicSharedMemorySize,
                         FLASH_SMEM);

    proj_kernel<<<dim3(NN / 128, NB), 256, PROJ_SMEM>>>(x, wq, bq, wk, bk, wv, bv);
    flash_mma_kernel<<<dim3(NN / BM, NB), 256, FLASH_SMEM>>>(x, gamma, out);
}